// round 8
// baseline (speedup 1.0000x reference)
#include <cuda_runtime.h>
#include <cuda_bf16.h>

#define NLEV  256
#define TN    258          // thresholds + 3 pads (indices 0..257)
#define NBINS 4096
#define BPT   (NBINS / 256)
#define VPT   2            // float4 per stream per thread => 8 elements/thread
#define FBIG  3.402823466e38f

// Monotone order-preserving float<->uint key (total order on finite floats).
__device__ __forceinline__ unsigned okey(float f) {
    unsigned u = __float_as_uint(f);
    return (u & 0x80000000u) ? ~u : (u | 0x80000000u);
}
__device__ __forceinline__ float oinv(unsigned k) {
    return __uint_as_float((k & 0x80000000u) ? (k ^ 0x80000000u) : ~k);
}

__global__ void __launch_bounds__(256, 5)
agc_quant_kernel(const float4* __restrict__ in4,
                 const float4* __restrict__ mn4,
                 const float*  __restrict__ uvals,
                 float* __restrict__ out_dq,
                 float* __restrict__ out_sym,
                 int n4, int n)
{
    __shared__ float  su[NLEV];       // codebook values
    __shared__ float  Ts[TN];         // scalar thresholds (+FBIG pads)
    __shared__ float2 F2[TN * 16];    // 33 KB fused (T, value), 16-way replicated
    __shared__ short  slut[NBINS];    // 8 KB conservative count seeds

    const int tid  = threadIdx.x;
    const int l16  = tid & 15;
    const int bdim = blockDim.x;

    if (tid < NLEV) su[tid] = uvals[tid];
    __syncthreads();

    // ---- Thresholds: T[i-1] = largest v where tie-break picks symbol i-1.
    // Pure-ALU bit-space binary search (no LDS in the loop) — validated exact.
    if (tid >= 1 && tid < NLEV) {
        float l = su[tid - 1], r = su[tid];
        unsigned klo = okey(l);
        unsigned khi = okey(r);
        #pragma unroll 1
        while (khi - klo > 1u) {
            unsigned km = klo + ((khi - klo) >> 1);
            float vm = oinv(km);
            if (fabsf(vm - l) <= fabsf(vm - r)) klo = km; else khi = km;
        }
        Ts[tid - 1] = oinv(klo);
    }
    if (tid == 0) { Ts[NLEV - 1] = FBIG; Ts[NLEV] = FBIG; Ts[NLEV + 1] = FBIG; }
    __syncthreads();

    // ---- Fused replicated table: F2[j*16 + r] = (T[j], su[min(j,255)])
    for (int i = tid; i < TN * 16; i += bdim) {
        int j = i >> 4;
        F2[i] = make_float2(Ts[j], su[j < NLEV ? j : NLEV - 1]);
    }

    const float lo    = su[0];
    const float hi    = su[NLEV - 1];
    const float w     = (hi - lo) * (1.0f / NBINS);
    const float inv_w = (float)NBINS / (hi - lo);
    const float c0    = -lo * inv_w;          // bin = trunc(fma(v, inv_w, c0))

    // ---- Seed LUT: slut[b] = count(T < fmaf(b-1, w, lo)) (one-bin guard =>
    // provable lower bound of count(T < v) for any v mapping to bin b).
    {
        const int b0 = tid * BPT;
        float x0 = fmaf((float)(b0 - 1), w, lo);
        int q = 0;
        #pragma unroll
        for (int s = 128; s >= 1; s >>= 1)
            if (Ts[q + s - 1] < x0) q += s;
        if (q > NLEV - 1) q = NLEV - 1;
        #pragma unroll
        for (int j = 0; j < BPT; j++) {
            int b = b0 + j;
            float xb = fmaf((float)(b - 1), w, lo);
            while (Ts[q] < xb) ++q;           // Ts pads stop the walk; q <= 255
            slut[b] = (short)q;
        }
    }
    __syncthreads();

    const int tile  = bdim * VPT;
    const int gstep = gridDim.x * tile;

    for (int base = blockIdx.x * tile + tid; base < n4; base += gstep) {

        if (base + (VPT - 1) * bdim < n4) {
            float4 x[VPT], mm[VPT];
            #pragma unroll
            for (int j = 0; j < VPT; j++) x[j]  = __ldcs(&in4[base + j * bdim]);
            #pragma unroll
            for (int j = 0; j < VPT; j++) mm[j] = __ldcs(&mn4[base + j * bdim]);

            float v[4 * VPT];
            #pragma unroll
            for (int j = 0; j < VPT; j++) {
                v[4*j+0] = x[j].x - mm[j].x;
                v[4*j+1] = x[j].y - mm[j].y;
                v[4*j+2] = x[j].z - mm[j].z;
                v[4*j+3] = x[j].w - mm[j].w;
            }

            int p[4 * VPT];
            #pragma unroll
            for (int e = 0; e < 4 * VPT; e++) {
                int b = (int)fmaf(v[e], inv_w, c0);
                b = b < 0 ? 0 : (b > NBINS - 1 ? NBINS - 1 : b);
                p[e] = slut[b];                        // conservative seed
            }

            float2 tv[4 * VPT];
            #pragma unroll
            for (int e = 0; e < 4 * VPT; e++)          // one LDS.64 each (<=2 phases)
                tv[e] = F2[(p[e] << 4) + l16];

            float dq[4 * VPT], sy[4 * VPT];
            #pragma unroll
            for (int e = 0; e < 4 * VPT; e++) {
                int q = p[e];
                float2 t = tv[e];
                while (t.x < v[e]) {                   // ~0.1 iters/elem expected
                    ++q;
                    t = F2[(q << 4) + l16];
                }
                sy[e] = (float)q;                      // sym = count(T < v), exact
                dq[e] = t.y;                           // su[sym], fused in the load
            }

            #pragma unroll
            for (int j = 0; j < VPT; j++) {
                __stcs(&reinterpret_cast<float4*>(out_dq)[base + j * bdim],
                       make_float4(dq[4*j+0] + mm[j].x, dq[4*j+1] + mm[j].y,
                                   dq[4*j+2] + mm[j].z, dq[4*j+3] + mm[j].w));
                __stcs(&reinterpret_cast<float4*>(out_sym)[base + j * bdim],
                       make_float4(sy[4*j+0], sy[4*j+1], sy[4*j+2], sy[4*j+3]));
            }
        } else {
            #pragma unroll
            for (int j = 0; j < VPT; j++) {
                int i = base + j * bdim;
                if (i >= n4) break;
                float4 x = in4[i];
                float4 m = mn4[i];
                float vv[4] = { x.x - m.x, x.y - m.y, x.z - m.z, x.w - m.w };
                float dq[4], sy[4];
                #pragma unroll
                for (int k = 0; k < 4; k++) {
                    int b = (int)fmaf(vv[k], inv_w, c0);
                    b = b < 0 ? 0 : (b > NBINS - 1 ? NBINS - 1 : b);
                    int q = slut[b];
                    float2 t = F2[(q << 4) + l16];
                    while (t.x < vv[k]) { ++q; t = F2[(q << 4) + l16]; }
                    sy[k] = (float)q;
                    dq[k] = t.y;
                }
                reinterpret_cast<float4*>(out_dq)[i] =
                    make_float4(dq[0] + m.x, dq[1] + m.y, dq[2] + m.z, dq[3] + m.w);
                reinterpret_cast<float4*>(out_sym)[i] =
                    make_float4(sy[0], sy[1], sy[2], sy[3]);
            }
        }
    }

    // Scalar float tail (n % 4 != 0) — block 0 only.
    if (blockIdx.x == 0) {
        const float* in1 = reinterpret_cast<const float*>(in4);
        const float* mn1 = reinterpret_cast<const float*>(mn4);
        for (int i = n4 * 4 + tid; i < n; i += bdim) {
            float vv = in1[i] - mn1[i];
            int b = (int)fmaf(vv, inv_w, c0);
            b = b < 0 ? 0 : (b > NBINS - 1 ? NBINS - 1 : b);
            int q = slut[b];
            float2 t = F2[(q << 4) + l16];
            while (t.x < vv) { ++q; t = F2[(q << 4) + l16]; }
            out_sym[i] = (float)q;
            out_dq[i]  = t.y + mn1[i];
        }
    }
}

extern "C" void kernel_launch(void* const* d_in, const int* in_sizes, int n_in,
                              void* d_out, int out_size)
{
    const float* inputs = (const float*)d_in[0];
    const float* means  = (const float*)d_in[1];
    const float* uvals  = (const float*)d_in[2];
    float* out = (float*)d_out;

    const int n  = out_size / 2;
    const int n4 = n / 4;

    float* out_dq  = out;
    float* out_sym = out + n;

    const int threads = 256;
    int blocks = 740;                        // 5 CTAs/SM on 148 SMs, grid-stride
    int maxb = (n4 + threads * VPT - 1) / (threads * VPT);
    if (blocks > maxb && maxb > 0) blocks = maxb;
    if (blocks < 1) blocks = 1;

    agc_quant_kernel<<<blocks, threads>>>(
        (const float4*)inputs, (const float4*)means, uvals,
        out_dq, out_sym, n4, n);
}

// round 9
// speedup vs baseline: 1.1599x; 1.1599x over previous
#include <cuda_runtime.h>
#include <cuda_bf16.h>

#define NLEV  256
#define NBINS 2048
#define VPT   2     // float4 per stream per thread => 8 elements/thread

__global__ void __launch_bounds__(256, 4)
agc_quant_kernel(const float4* __restrict__ in4,
                 const float4* __restrict__ mn4,
                 const float*  __restrict__ uvals,
                 float* __restrict__ out_dq,
                 float* __restrict__ out_sym,
                 int n4, int n)
{
    __shared__ float us[NLEV * 32];              // 32 KB replicated codebook
    __shared__ __align__(16) short slut[NBINS];  // 4 KB conservative seed LUT

    const int tid  = threadIdx.x;
    const int lane = tid & 31;
    const int bdim = blockDim.x;

    for (int i = tid; i < NLEV * 32; i += bdim)
        us[i] = uvals[i >> 5];
    __syncthreads();

    const float lo    = us[lane];
    const float hi    = us[((NLEV - 1) << 5) + lane];
    const float w     = (hi - lo) * (1.0f / NBINS);
    const float inv_w = (float)NBINS / (hi - lo);

    // slut[b] = count(u < fmaf(b-1, w, lo)) : one-bin-conservative (never overcounts)
    for (int b = tid; b < NBINS; b += bdim) {
        float bs = fmaf((float)(b - 1), w, lo);
        int pos = 0;
        #pragma unroll
        for (int s = 128; s >= 1; s >>= 1) {
            if (us[((pos + s - 1) << 5) + lane] < bs) pos += s;
        }
        slut[b] = (short)pos;
    }
    __syncthreads();

    const int tile  = bdim * VPT;
    const int gstep = gridDim.x * tile;

    int base = blockIdx.x * tile + tid;

    // ---- software pipeline: prefetch next iteration's loads before compute ----
    float4 xa[VPT], ma[VPT];
    bool fastA = (base < n4) && (base + (VPT - 1) * bdim < n4);
    if (fastA) {
        #pragma unroll
        for (int j = 0; j < VPT; j++) xa[j] = __ldcs(&in4[base + j * bdim]);
        #pragma unroll
        for (int j = 0; j < VPT; j++) ma[j] = __ldcs(&mn4[base + j * bdim]);
    }

    while (base < n4) {
        const int nbase = base + gstep;

        // prefetch iteration k+1 (in flight during compute of iteration k)
        float4 xb[VPT], mb[VPT];
        const bool fastB = (nbase < n4) && (nbase + (VPT - 1) * bdim < n4);
        if (fastB) {
            #pragma unroll
            for (int j = 0; j < VPT; j++) xb[j] = __ldcs(&in4[nbase + j * bdim]);
            #pragma unroll
            for (int j = 0; j < VPT; j++) mb[j] = __ldcs(&mn4[nbase + j * bdim]);
        }

        if (fastA) {
            float v[4 * VPT];
            #pragma unroll
            for (int j = 0; j < VPT; j++) {
                v[4*j+0] = xa[j].x - ma[j].x;
                v[4*j+1] = xa[j].y - ma[j].y;
                v[4*j+2] = xa[j].z - ma[j].z;
                v[4*j+3] = xa[j].w - ma[j].w;
            }

            int p[4 * VPT];
            #pragma unroll
            for (int e = 0; e < 4 * VPT; e++) {
                int b = (int)((v[e] - lo) * inv_w);
                b = b < 0 ? 0 : (b > NBINS - 1 ? NBINS - 1 : b);
                p[e] = slut[b];                         // conservative seed
            }
            #pragma unroll
            for (int e = 0; e < 4 * VPT; e++) {
                int q = p[e];
                while (q < NLEV && us[(q << 5) + lane] < v[e]) ++q;  // exact count(u<v)
                p[e] = q;
            }

            float dq[4 * VPT], sy[4 * VPT];
            #pragma unroll
            for (int e = 0; e < 4 * VPT; e++) {
                int c = p[e];
                c = c < 1 ? 1 : (c > NLEV - 1 ? NLEV - 1 : c);
                float left  = us[((c - 1) << 5) + lane];
                float right = us[(c << 5) + lane];
                bool tl = fabsf(v[e] - left) <= fabsf(v[e] - right);
                sy[e] = (float)(tl ? c - 1 : c);
                dq[e] = tl ? left : right;
            }
            #pragma unroll
            for (int j = 0; j < VPT; j++) {
                __stcs(&reinterpret_cast<float4*>(out_dq)[base + j * bdim],
                       make_float4(dq[4*j+0] + ma[j].x, dq[4*j+1] + ma[j].y,
                                   dq[4*j+2] + ma[j].z, dq[4*j+3] + ma[j].w));
                __stcs(&reinterpret_cast<float4*>(out_sym)[base + j * bdim],
                       make_float4(sy[4*j+0], sy[4*j+1], sy[4*j+2], sy[4*j+3]));
            }
        } else {
            // guarded path (last partial tile): loads done inline, exact math
            #pragma unroll
            for (int j = 0; j < VPT; j++) {
                int i = base + j * bdim;
                if (i >= n4) break;
                float4 x = in4[i];
                float4 m = mn4[i];
                float vv[4] = { x.x - m.x, x.y - m.y, x.z - m.z, x.w - m.w };
                float dq[4], sy[4];
                #pragma unroll
                for (int k = 0; k < 4; k++) {
                    int b = (int)((vv[k] - lo) * inv_w);
                    b = b < 0 ? 0 : (b > NBINS - 1 ? NBINS - 1 : b);
                    int q = slut[b];
                    while (q < NLEV && us[(q << 5) + lane] < vv[k]) ++q;
                    int c = q < 1 ? 1 : (q > NLEV - 1 ? NLEV - 1 : q);
                    float left  = us[((c - 1) << 5) + lane];
                    float right = us[(c << 5) + lane];
                    bool tl = fabsf(vv[k] - left) <= fabsf(vv[k] - right);
                    sy[k] = (float)(tl ? c - 1 : c);
                    dq[k] = tl ? left : right;
                }
                reinterpret_cast<float4*>(out_dq)[i] =
                    make_float4(dq[0] + m.x, dq[1] + m.y, dq[2] + m.z, dq[3] + m.w);
                reinterpret_cast<float4*>(out_sym)[i] =
                    make_float4(sy[0], sy[1], sy[2], sy[3]);
            }
        }

        base  = nbase;
        fastA = fastB;
        #pragma unroll
        for (int j = 0; j < VPT; j++) { xa[j] = xb[j]; ma[j] = mb[j]; }
    }

    // Scalar float tail (n % 4 != 0) — block 0 only.
    if (blockIdx.x == 0) {
        const float* in1 = reinterpret_cast<const float*>(in4);
        const float* mn1 = reinterpret_cast<const float*>(mn4);
        for (int i = n4 * 4 + tid; i < n; i += bdim) {
            float vv = in1[i] - mn1[i];
            int b = (int)((vv - lo) * inv_w);
            b = b < 0 ? 0 : (b > NBINS - 1 ? NBINS - 1 : b);
            int q = slut[b];
            while (q < NLEV && us[(q << 5) + lane] < vv) ++q;
            int c = q < 1 ? 1 : (q > NLEV - 1 ? NLEV - 1 : q);
            float left  = us[((c - 1) << 5) + lane];
            float right = us[(c << 5) + lane];
            bool tl = fabsf(vv - left) <= fabsf(vv - right);
            out_sym[i] = (float)(tl ? c - 1 : c);
            out_dq[i]  = (tl ? left : right) + mn1[i];
        }
    }
}

extern "C" void kernel_launch(void* const* d_in, const int* in_sizes, int n_in,
                              void* d_out, int out_size)
{
    const float* inputs = (const float*)d_in[0];
    const float* means  = (const float*)d_in[1];
    const float* uvals  = (const float*)d_in[2];
    float* out = (float*)d_out;

    const int n  = out_size / 2;
    const int n4 = n / 4;

    float* out_dq  = out;
    float* out_sym = out + n;

    const int threads = 256;
    int blocks = 592;                        // 4 CTAs/SM on 148 SMs, ~10 pipelined iters
    int maxb = (n4 + threads * VPT - 1) / (threads * VPT);
    if (blocks > maxb && maxb > 0) blocks = maxb;
    if (blocks < 1) blocks = 1;

    agc_quant_kernel<<<blocks, threads>>>(
        (const float4*)inputs, (const float4*)means, uvals,
        out_dq, out_sym, n4, n);
}

// round 10
// speedup vs baseline: 1.2245x; 1.0557x over previous
#include <cuda_runtime.h>
#include <cuda_bf16.h>

#define NLEV  256
#define NBINS 1024
#define VPT   2     // float4 per stream per thread => 8 elements/thread

__global__ void __launch_bounds__(256, 4)
agc_quant_kernel(const float4* __restrict__ in4,
                 const float4* __restrict__ mn4,
                 const float*  __restrict__ uvals,
                 float* __restrict__ out_dq,
                 float* __restrict__ out_sym,
                 int n4, int n)
{
    __shared__ float us[NLEV * 32];                       // 32 KB replicated codebook
    __shared__ __align__(16) unsigned char slut[NBINS * 16]; // 16 KB, 16-way replicated seeds

    const int tid  = threadIdx.x;
    const int lane = tid & 31;
    const int l16  = tid & 15;
    const int bdim = blockDim.x;

    for (int i = tid; i < NLEV * 32; i += bdim)
        us[i] = uvals[i >> 5];
    __syncthreads();

    const float lo    = us[lane];
    const float hi    = us[((NLEV - 1) << 5) + lane];
    const float w     = (hi - lo) * (1.0f / NBINS);
    const float inv_w = (float)NBINS / (hi - lo);

    // seed(b) = min(count(u < binstart(b-1)), 255): one-bin-conservative lower
    // bound of count(u < v) for any v in bin b.  Splat 16 replicas per STS.128.
    for (int b = tid; b < NBINS; b += bdim) {
        float bs = fmaf((float)(b - 1), w, lo);
        int pos = 0;
        #pragma unroll
        for (int s = 128; s >= 1; s >>= 1) {
            if (us[((pos + s - 1) << 5) + lane] < bs) pos += s;
        }
        pos = pos > 255 ? 255 : pos;
        unsigned pp = (unsigned)pos * 0x01010101u;
        *reinterpret_cast<uint4*>(&slut[b << 4]) = make_uint4(pp, pp, pp, pp);
    }
    __syncthreads();

    const int tile  = bdim * VPT;
    const int gstep = gridDim.x * tile;

    int base = blockIdx.x * tile + tid;

    // ---- software pipeline: prefetch next iteration's loads before compute ----
    float4 xa[VPT], ma[VPT];
    bool fastA = (base < n4) && (base + (VPT - 1) * bdim < n4);
    if (fastA) {
        #pragma unroll
        for (int j = 0; j < VPT; j++) xa[j] = __ldcs(&in4[base + j * bdim]);
        #pragma unroll
        for (int j = 0; j < VPT; j++) ma[j] = __ldcs(&mn4[base + j * bdim]);
    }

    while (base < n4) {
        const int nbase = base + gstep;

        float4 xb[VPT], mb[VPT];
        const bool fastB = (nbase < n4) && (nbase + (VPT - 1) * bdim < n4);
        if (fastB) {
            #pragma unroll
            for (int j = 0; j < VPT; j++) xb[j] = __ldcs(&in4[nbase + j * bdim]);
            #pragma unroll
            for (int j = 0; j < VPT; j++) mb[j] = __ldcs(&mn4[nbase + j * bdim]);
        }

        if (fastA) {
            float v[4 * VPT];
            #pragma unroll
            for (int j = 0; j < VPT; j++) {
                v[4*j+0] = xa[j].x - ma[j].x;
                v[4*j+1] = xa[j].y - ma[j].y;
                v[4*j+2] = xa[j].z - ma[j].z;
                v[4*j+3] = xa[j].w - ma[j].w;
            }

            int p[4 * VPT];
            #pragma unroll
            for (int e = 0; e < 4 * VPT; e++) {
                int b = (int)((v[e] - lo) * inv_w);
                b = b < 0 ? 0 : (b > NBINS - 1 ? NBINS - 1 : b);
                p[e] = (int)slut[(b << 4) + l16];       // replicated seed, ~1.7 phases
            }
            #pragma unroll
            for (int e = 0; e < 4 * VPT; e++) {
                int q = p[e];
                while (q < NLEV && us[(q << 5) + lane] < v[e]) ++q;  // exact count(u<v)
                p[e] = q;
            }

            float dq[4 * VPT], sy[4 * VPT];
            #pragma unroll
            for (int e = 0; e < 4 * VPT; e++) {
                int c = p[e];
                c = c < 1 ? 1 : (c > NLEV - 1 ? NLEV - 1 : c);
                float left  = us[((c - 1) << 5) + lane];
                float right = us[(c << 5) + lane];
                bool tl = fabsf(v[e] - left) <= fabsf(v[e] - right);
                sy[e] = (float)(tl ? c - 1 : c);
                dq[e] = tl ? left : right;
            }
            #pragma unroll
            for (int j = 0; j < VPT; j++) {
                __stcs(&reinterpret_cast<float4*>(out_dq)[base + j * bdim],
                       make_float4(dq[4*j+0] + ma[j].x, dq[4*j+1] + ma[j].y,
                                   dq[4*j+2] + ma[j].z, dq[4*j+3] + ma[j].w));
                __stcs(&reinterpret_cast<float4*>(out_sym)[base + j * bdim],
                       make_float4(sy[4*j+0], sy[4*j+1], sy[4*j+2], sy[4*j+3]));
            }
        } else {
            // guarded path (last partial tile)
            #pragma unroll
            for (int j = 0; j < VPT; j++) {
                int i = base + j * bdim;
                if (i >= n4) break;
                float4 x = in4[i];
                float4 m = mn4[i];
                float vv[4] = { x.x - m.x, x.y - m.y, x.z - m.z, x.w - m.w };
                float dq[4], sy[4];
                #pragma unroll
                for (int k = 0; k < 4; k++) {
                    int b = (int)((vv[k] - lo) * inv_w);
                    b = b < 0 ? 0 : (b > NBINS - 1 ? NBINS - 1 : b);
                    int q = (int)slut[(b << 4) + l16];
                    while (q < NLEV && us[(q << 5) + lane] < vv[k]) ++q;
                    int c = q < 1 ? 1 : (q > NLEV - 1 ? NLEV - 1 : q);
                    float left  = us[((c - 1) << 5) + lane];
                    float right = us[(c << 5) + lane];
                    bool tl = fabsf(vv[k] - left) <= fabsf(vv[k] - right);
                    sy[k] = (float)(tl ? c - 1 : c);
                    dq[k] = tl ? left : right;
                }
                reinterpret_cast<float4*>(out_dq)[i] =
                    make_float4(dq[0] + m.x, dq[1] + m.y, dq[2] + m.z, dq[3] + m.w);
                reinterpret_cast<float4*>(out_sym)[i] =
                    make_float4(sy[0], sy[1], sy[2], sy[3]);
            }
        }

        base  = nbase;
        fastA = fastB;
        #pragma unroll
        for (int j = 0; j < VPT; j++) { xa[j] = xb[j]; ma[j] = mb[j]; }
    }

    // Scalar float tail (n % 4 != 0) — block 0 only.
    if (blockIdx.x == 0) {
        const float* in1 = reinterpret_cast<const float*>(in4);
        const float* mn1 = reinterpret_cast<const float*>(mn4);
        for (int i = n4 * 4 + tid; i < n; i += bdim) {
            float vv = in1[i] - mn1[i];
            int b = (int)((vv - lo) * inv_w);
            b = b < 0 ? 0 : (b > NBINS - 1 ? NBINS - 1 : b);
            int q = (int)slut[(b << 4) + l16];
            while (q < NLEV && us[(q << 5) + lane] < vv) ++q;
            int c = q < 1 ? 1 : (q > NLEV - 1 ? NLEV - 1 : q);
            float left  = us[((c - 1) << 5) + lane];
            float right = us[(c << 5) + lane];
            bool tl = fabsf(vv - left) <= fabsf(vv - right);
            out_sym[i] = (float)(tl ? c - 1 : c);
            out_dq[i]  = (tl ? left : right) + mn1[i];
        }
    }
}

extern "C" void kernel_launch(void* const* d_in, const int* in_sizes, int n_in,
                              void* d_out, int out_size)
{
    const float* inputs = (const float*)d_in[0];
    const float* means  = (const float*)d_in[1];
    const float* uvals  = (const float*)d_in[2];
    float* out = (float*)d_out;

    const int n  = out_size / 2;
    const int n4 = n / 4;

    float* out_dq  = out;
    float* out_sym = out + n;

    const int threads = 256;
    int blocks = 592;                        // 4 CTAs/SM on 148 SMs, pipelined grid-stride
    int maxb = (n4 + threads * VPT - 1) / (threads * VPT);
    if (blocks > maxb && maxb > 0) blocks = maxb;
    if (blocks < 1) blocks = 1;

    agc_quant_kernel<<<blocks, threads>>>(
        (const float4*)inputs, (const float4*)means, uvals,
        out_dq, out_sym, n4, n);
}